// round 2
// baseline (speedup 1.0000x reference)
#include <cuda_runtime.h>
#include <math.h>
#include <stdint.h>

#define BB 16
#define NN 2048
#define KK 16
#define NPTS (BB*NN)   // 32768

// ---------------- scratch (device globals; no allocation allowed) ----------------
__device__ float gA[NPTS*128];
__device__ float gB[NPTS*128];
__device__ int   gIdx[NPTS*KK];
__device__ float gSq[NPTS];
__device__ float gPool[BB*1024];
__device__ float gY[BB*1024];

__device__ __forceinline__ void atomicMaxF(float* addr, float val){
    int old = __float_as_int(*addr);
    while (__int_as_float(old) < val) {
        int prev = atomicCAS((int*)addr, old, __float_as_int(val));
        if (prev == old) break;
        old = prev;
    }
}

// ---------------- squared norms: one warp per row ----------------
__global__ void k_sq(const float* __restrict__ H, float* __restrict__ SQ, int C){
    int gt = blockIdx.x*blockDim.x + threadIdx.x;
    int row = gt >> 5;
    int lane = gt & 31;
    if (row >= NPTS) return;
    const float* p = H + (size_t)row*C;
    float s = 0.f;
    for (int c = lane; c < C; c += 32) { float v = p[c]; s = fmaf(v,v,s); }
    #pragma unroll
    for (int o=16;o>0;o>>=1) s += __shfl_down_sync(0xffffffffu, s, o);
    if (lane==0) SQ[row] = s;
}

// ---------------- kNN: tiled distance + fused top-16 ----------------
// grid (N/128, B), 256 threads. d(i,j) = sq_i + sq_j - 2*dot(h_i,h_j).
// Top-16 kept sorted ascending per i in shared; stable insertion + evict-last
// reproduces jax top_k tie-breaking (lowest index wins).
template<int C>
__global__ __launch_bounds__(256,1) void k_knn(const float* __restrict__ H,
                                               const float* __restrict__ SQ,
                                               int* __restrict__ IDX){
    constexpr int CHUNK = (C < 32) ? C : 32;
    extern __shared__ float sm[];
    float* sA   = sm;                   // [C][132] transposed i-tile
    float* sB   = sA + C*132;           // [CHUNK][132] transposed j-chunk
    float* sD   = sB + CHUNK*132;       // [128][129] dot tile
    float* sSqB = sD + 128*129;         // [128]
    float* topd = sSqB + 128;           // [128][17]
    int*   topi = (int*)(topd + 128*17);// [128][17]

    const int t  = threadIdx.x;
    const int tx = t & 15, ty = t >> 4;
    const int b  = blockIdx.y;
    const int i0 = blockIdx.x * 128;
    const size_t baseRow = (size_t)b * NN;

    for (int e = t; e < 128*C; e += 256) {
        int i = e / C, c = e - i*C;
        sA[c*132 + i] = H[(baseRow + i0 + i)*(size_t)C + c];
    }
    for (int e = t; e < 128*16; e += 256) {
        int i = e >> 4, s = e & 15;
        topd[i*17+s] = INFINITY;
        topi[i*17+s] = 0;
    }
    float sqa = (t < 128) ? SQ[baseRow + i0 + t] : 0.f;

    for (int jt = 0; jt < NN/128; ++jt) {
        __syncthreads();                      // protects sSqB/sD vs previous scan
        const int j0 = jt*128;
        if (t < 128) sSqB[t] = SQ[baseRow + j0 + t];

        float acc[8][8];
        #pragma unroll
        for (int a=0;a<8;a++)
            #pragma unroll
            for (int c=0;c<8;c++) acc[a][c]=0.f;

        for (int c0 = 0; c0 < C; c0 += CHUNK) {
            __syncthreads();
            for (int e = t; e < 128*CHUNK; e += 256) {
                int j = e / CHUNK, c = e - j*CHUNK;
                sB[c*132 + j] = H[(baseRow + j0 + j)*(size_t)C + c0 + c];
            }
            __syncthreads();
            #pragma unroll 4
            for (int c = 0; c < CHUNK; ++c) {
                float av[8], bv[8];
                #pragma unroll
                for (int r=0;r<8;r++) av[r] = sA[(c0+c)*132 + ty + 16*r];
                #pragma unroll
                for (int r=0;r<8;r++) bv[r] = sB[c*132 + tx + 16*r];
                #pragma unroll
                for (int ri=0;ri<8;ri++)
                    #pragma unroll
                    for (int rj=0;rj<8;rj++)
                        acc[ri][rj] = fmaf(av[ri], bv[rj], acc[ri][rj]);
            }
        }
        #pragma unroll
        for (int ri=0;ri<8;ri++)
            #pragma unroll
            for (int rj=0;rj<8;rj++)
                sD[(ty+16*ri)*129 + tx+16*rj] = acc[ri][rj];
        __syncthreads();

        if (t < 128) {
            float* td = topd + t*17;
            int*   ti = topi + t*17;
            const float* drow = sD + t*129;
            float worst = td[15];
            for (int jj = 0; jj < 128; ++jj) {
                float d = sqa + sSqB[jj] - 2.f*drow[jj];
                if (d < worst) {
                    int pos = 15;
                    while (pos > 0 && td[pos-1] > d) {
                        td[pos] = td[pos-1];
                        ti[pos] = ti[pos-1];
                        --pos;
                    }
                    td[pos] = d;
                    ti[pos] = j0 + jj;
                    worst = td[15];
                }
            }
        }
    }
    __syncthreads();
    if (t < 128) {
        int* o = IDX + (baseRow + i0 + t)*KK;
        #pragma unroll
        for (int s=0;s<16;s++) o[s] = topi[t*17+s];
    }
}

// ---------------- cov features: [x, cov(knn xyz).flatten(9)] -> 12 ch ----------------
__global__ void k_cov(const float* __restrict__ X, const int* __restrict__ IDX,
                      float* __restrict__ OUT){
    int p = blockIdx.x*blockDim.x + threadIdx.x;
    if (p >= NPTS) return;
    int b = p >> 11;
    const int* id = IDX + (size_t)p*KK;
    float px[16], py[16], pz[16];
    float mx=0.f,my=0.f,mz=0.f;
    #pragma unroll
    for (int k=0;k<16;k++){
        int j = id[k];
        const float* q = X + ((size_t)(b<<11) + j)*3;
        px[k]=q[0]; py[k]=q[1]; pz[k]=q[2];
        mx+=px[k]; my+=py[k]; mz+=pz[k];
    }
    mx *= (1.f/16.f); my *= (1.f/16.f); mz *= (1.f/16.f);
    float c00=0,c01=0,c02=0,c11=0,c12=0,c22=0;
    #pragma unroll
    for (int k=0;k<16;k++){
        float cx=px[k]-mx, cy=py[k]-my, cz=pz[k]-mz;
        c00=fmaf(cx,cx,c00); c01=fmaf(cx,cy,c01); c02=fmaf(cx,cz,c02);
        c11=fmaf(cy,cy,c11); c12=fmaf(cy,cz,c12); c22=fmaf(cz,cz,c22);
    }
    const float* xi = X + (size_t)p*3;
    float* o = OUT + (size_t)p*12;
    o[0]=xi[0]; o[1]=xi[1]; o[2]=xi[2];
    o[3]=c00; o[4]=c01; o[5]=c02;
    o[6]=c01; o[7]=c11; o[8]=c12;
    o[9]=c02; o[10]=c12; o[11]=c22;
}

// ---------------- pointwise dense (kernel_size=1 conv), optional BN+ReLU ----------------
// 64-row tiles, each thread 2 rows x 4 cols.
template<int CIN,int COUT,int RELU,int BN>
__global__ __launch_bounds__(256) void k_dense(const float* __restrict__ X,
        const float* __restrict__ W, const float* __restrict__ bias,
        const float* __restrict__ bg, const float* __restrict__ bb,
        const float* __restrict__ bm, const float* __restrict__ bv,
        float* __restrict__ OUT){
    extern __shared__ float sm[];
    float* Xs = sm;                  // [64][CIN+1]
    float* Ws = Xs + 64*(CIN+1);     // [CIN][COUT]
    const int t = threadIdx.x;
    const size_t row0 = (size_t)blockIdx.x * 64;
    for (int e = t; e < 64*CIN; e += 256) {
        int r = e / CIN, k = e - r*CIN;
        Xs[r*(CIN+1)+k] = X[row0*CIN + e];
    }
    for (int e = t; e < CIN*COUT; e += 256) Ws[e] = W[e];
    __syncthreads();
    constexpr int CQ = COUT/4;
    for (int q = t; q < 32*CQ; q += 256) {
        int rp = q / CQ;
        int c4 = (q - rp*CQ)*4;
        float4 b4 = *(const float4*)(bias + c4);
        float a0[4] = {b4.x,b4.y,b4.z,b4.w};
        float a1[4] = {b4.x,b4.y,b4.z,b4.w};
        #pragma unroll 8
        for (int k=0;k<CIN;k++){
            float x0 = Xs[rp*(CIN+1)+k];
            float x1 = Xs[(rp+32)*(CIN+1)+k];
            float4 w = *(const float4*)(Ws + k*COUT + c4);
            a0[0]=fmaf(x0,w.x,a0[0]); a0[1]=fmaf(x0,w.y,a0[1]);
            a0[2]=fmaf(x0,w.z,a0[2]); a0[3]=fmaf(x0,w.w,a0[3]);
            a1[0]=fmaf(x1,w.x,a1[0]); a1[1]=fmaf(x1,w.y,a1[1]);
            a1[2]=fmaf(x1,w.z,a1[2]); a1[3]=fmaf(x1,w.w,a1[3]);
        }
        #pragma unroll
        for (int u=0;u<4;u++){
            float v0=a0[u], v1=a1[u];
            if (BN){
                int c = c4+u;
                float s   = bg[c]*rsqrtf(bv[c]+1e-3f);
                float off = bb[c] - bm[c]*s;
                v0 = fmaf(v0,s,off); v1 = fmaf(v1,s,off);
            }
            if (RELU){ v0=fmaxf(v0,0.f); v1=fmaxf(v1,0.f); }
            a0[u]=v0; a1[u]=v1;
        }
        *(float4*)(OUT + (row0+rp)*COUT + c4)    = make_float4(a0[0],a0[1],a0[2],a0[3]);
        *(float4*)(OUT + (row0+rp+32)*COUT + c4) = make_float4(a1[0],a1[1],a1[2],a1[3]);
    }
}

// ---------------- gather neighbors + max over k ----------------
template<int C>
__global__ void k_gmax(const float* __restrict__ H, const int* __restrict__ IDX,
                       float* __restrict__ OUT){
    constexpr int CQ = C/4;
    int e = blockIdx.x*blockDim.x + threadIdx.x;
    if (e >= NPTS*CQ) return;
    int p = e / CQ, c4 = (e - p*CQ)*4;
    int b = p >> 11;
    const int* id = IDX + (size_t)p*KK;
    float4 m = make_float4(-INFINITY,-INFINITY,-INFINITY,-INFINITY);
    #pragma unroll
    for (int k=0;k<16;k++){
        int j = id[k];
        float4 v = *(const float4*)(H + ((size_t)(b<<11)+j)*C + c4);
        m.x=fmaxf(m.x,v.x); m.y=fmaxf(m.y,v.y);
        m.z=fmaxf(m.z,v.z); m.w=fmaxf(m.w,v.w);
    }
    *(float4*)(OUT + (size_t)p*C + c4) = m;
}

// ---------------- 128->1024 GEMM fused with bias + global max over N ----------------
// grid (1024/128, N/128, B); 256 threads; 8x8 register micro-tiles.
__global__ __launch_bounds__(256,1) void k_gemm_pool(const float* __restrict__ X,
        const float* __restrict__ W, const float* __restrict__ bias,
        float* __restrict__ pool){
    extern __shared__ float sm[];
    float* XsT  = sm;              // [128 k][129 i]
    float* Ws   = XsT + 128*129;   // [128 k][129 c]
    float* sred = Ws  + 128*129;   // [128 c][17]
    const int t = threadIdx.x, tx = t & 15, ty = t >> 4;
    const int b = blockIdx.z;
    const size_t row0 = (size_t)b*NN + (size_t)blockIdx.y*128;
    const int c0 = blockIdx.x*128;

    for (int e=t; e<128*128; e+=256){
        int i = e >> 7, k = e & 127;
        XsT[k*129+i] = X[row0*128 + e];
    }
    for (int e=t; e<128*128; e+=256){
        int k = e >> 7, c = e & 127;
        Ws[k*129+c] = W[(size_t)k*1024 + c0 + c];
    }
    __syncthreads();

    float acc[8][8];
    #pragma unroll
    for (int a=0;a<8;a++)
        #pragma unroll
        for (int c=0;c<8;c++) acc[a][c]=0.f;

    #pragma unroll 4
    for (int k=0;k<128;k++){
        float av[8], wv[8];
        #pragma unroll
        for (int r=0;r<8;r++) av[r] = XsT[k*129 + ty + 16*r];
        #pragma unroll
        for (int r=0;r<8;r++) wv[r] = Ws[k*129 + tx + 16*r];
        #pragma unroll
        for (int ri=0;ri<8;ri++)
            #pragma unroll
            for (int rj=0;rj<8;rj++)
                acc[ri][rj] = fmaf(av[ri], wv[rj], acc[ri][rj]);
    }
    #pragma unroll
    for (int rj=0;rj<8;rj++){
        float m = acc[0][rj];
        #pragma unroll
        for (int ri=1;ri<8;ri++) m = fmaxf(m, acc[ri][rj]);
        sred[(tx+16*rj)*17 + ty] = m;
    }
    __syncthreads();
    if (t < 128){
        float m = sred[t*17];
        #pragma unroll
        for (int q=1;q<16;q++) m = fmaxf(m, sred[t*17+q]);
        m += bias[c0 + t];
        atomicMaxF(&pool[b*1024 + c0 + t], m);
    }
}

__global__ void k_init(float* __restrict__ p, int n){
    int e = blockIdx.x*blockDim.x + threadIdx.x;
    if (e < n) p[e] = -INFINITY;
}

// ---------------- tiny FC layers over pooled [B, CIN] ----------------
template<int CIN,int COUT,int RELU>
__global__ __launch_bounds__(256) void k_fc(const float* __restrict__ IN,
        const float* __restrict__ W, const float* __restrict__ bias,
        float* __restrict__ OUT){
    __shared__ float Ps[CIN];
    const int t = threadIdx.x;
    const int b = blockIdx.y;
    const int c = blockIdx.x*256 + t;
    for (int e=t;e<CIN;e+=256) Ps[e]=IN[b*CIN+e];
    __syncthreads();
    float acc = bias[c];
    #pragma unroll 8
    for (int k=0;k<CIN;k++) acc = fmaf(Ps[k], W[(size_t)k*COUT + c], acc);
    if (RELU) acc = fmaxf(acc, 0.f);
    OUT[b*COUT + c] = acc;
}

// ---------------- host ----------------
static inline int knn_smem(int C){
    int ch = C < 32 ? C : 32;
    return (C*132 + ch*132 + 128*129 + 128 + 128*17 + 128*17)*4;
}
static inline int dense_smem(int cin, int cout){
    return (64*(cin+1) + cin*cout)*4;
}

extern "C" void kernel_launch(void* const* d_in, const int* in_sizes, int n_in,
                              void* d_out, int out_size){
    const float* x    = (const float*)d_in[0];
    const float* c1w  = (const float*)d_in[1];
    const float* c1b  = (const float*)d_in[2];
    const float* c2w  = (const float*)d_in[3];
    const float* c2b  = (const float*)d_in[4];
    const float* c3w  = (const float*)d_in[5];
    const float* c3b  = (const float*)d_in[6];
    const float* g1lw = (const float*)d_in[7];
    const float* g1lb = (const float*)d_in[8];
    const float* g1cw = (const float*)d_in[9];
    const float* g1cb = (const float*)d_in[10];
    const float* g2lw = (const float*)d_in[11];
    const float* g2lb = (const float*)d_in[12];
    const float* g2cw = (const float*)d_in[13];
    const float* g2cb = (const float*)d_in[14];
    const float* c4w  = (const float*)d_in[15];
    const float* c4b  = (const float*)d_in[16];
    const float* c5w  = (const float*)d_in[17];
    const float* c5b  = (const float*)d_in[18];
    const float* bn1g = (const float*)d_in[19];
    const float* bn1b = (const float*)d_in[20];
    const float* bn1m = (const float*)d_in[21];
    const float* bn1v = (const float*)d_in[22];
    const float* bn2g = (const float*)d_in[23];
    const float* bn2b = (const float*)d_in[24];
    const float* bn2m = (const float*)d_in[25];
    const float* bn2v = (const float*)d_in[26];
    const float* bn3g = (const float*)d_in[27];
    const float* bn3b = (const float*)d_in[28];
    const float* bn3m = (const float*)d_in[29];
    const float* bn3v = (const float*)d_in[30];
    float* out = (float*)d_out;

    float *A,*B,*SQ,*POOL,*Y; int* ID;
    cudaGetSymbolAddress((void**)&A, gA);
    cudaGetSymbolAddress((void**)&B, gB);
    cudaGetSymbolAddress((void**)&SQ, gSq);
    cudaGetSymbolAddress((void**)&POOL, gPool);
    cudaGetSymbolAddress((void**)&Y, gY);
    cudaGetSymbolAddress((void**)&ID, gIdx);

    // opt-in shared memory sizes (idempotent)
    cudaFuncSetAttribute(k_knn<3>,   cudaFuncAttributeMaxDynamicSharedMemorySize, knn_smem(3));
    cudaFuncSetAttribute(k_knn<64>,  cudaFuncAttributeMaxDynamicSharedMemorySize, knn_smem(64));
    cudaFuncSetAttribute(k_knn<128>, cudaFuncAttributeMaxDynamicSharedMemorySize, knn_smem(128));
    cudaFuncSetAttribute(k_gemm_pool, cudaFuncAttributeMaxDynamicSharedMemorySize,
                         (128*129*2 + 128*17)*4);
    cudaFuncSetAttribute((void*)k_dense<64,128,1,0>, cudaFuncAttributeMaxDynamicSharedMemorySize,
                         dense_smem(64,128));
    cudaFuncSetAttribute((void*)k_dense<128,128,0,0>, cudaFuncAttributeMaxDynamicSharedMemorySize,
                         dense_smem(128,128));

    const dim3 knnGrid(NN/128, BB);

    // stage 0: knn on xyz + covariance features
    k_sq<<<(NPTS*32)/256, 256>>>(x, SQ, 3);
    k_knn<3><<<knnGrid, 256, knn_smem(3)>>>(x, SQ, ID);
    k_cov<<<NPTS/256, 256>>>(x, ID, A);                       // A: [*,12]

    // MLP stack with BN+ReLU
    k_dense<12,12,1,1><<<NPTS/64, 256, dense_smem(12,12)>>>(A, c1w, c1b, bn1g,bn1b,bn1m,bn1v, B);
    k_dense<12,64,1,1><<<NPTS/64, 256, dense_smem(12,64)>>>(B, c2w, c2b, bn2g,bn2b,bn2m,bn2v, A);
    k_dense<64,64,1,1><<<NPTS/64, 256, dense_smem(64,64)>>>(A, c3w, c3b, bn3g,bn3b,bn3m,bn3v, B); // h64 in B

    // graph layer 1 (C=64 -> 128, relu)
    k_sq<<<(NPTS*32)/256, 256>>>(B, SQ, 64);
    k_knn<64><<<knnGrid, 256, knn_smem(64)>>>(B, SQ, ID);
    k_gmax<64><<<(NPTS*16)/256, 256>>>(B, ID, A);
    k_dense<64,64,0,0><<<NPTS/64, 256, dense_smem(64,64)>>>(A, g1lw, g1lb, 0,0,0,0, B);
    k_dense<64,128,1,0><<<NPTS/64, 256, dense_smem(64,128)>>>(B, g1cw, g1cb, 0,0,0,0, A); // h128 in A

    // graph layer 2 (C=128 -> 1024, no relu) fused with global max pool
    k_sq<<<(NPTS*32)/256, 256>>>(A, SQ, 128);
    k_knn<128><<<knnGrid, 256, knn_smem(128)>>>(A, SQ, ID);
    k_gmax<128><<<(NPTS*32)/256, 256>>>(A, ID, B);
    k_dense<128,128,0,0><<<NPTS/64, 256, dense_smem(128,128)>>>(B, g2lw, g2lb, 0,0,0,0, A);
    k_init<<<(BB*1024)/256, 256>>>(POOL, BB*1024);
    k_gemm_pool<<<dim3(1024/128, NN/128, BB), 256, (128*129*2 + 128*17)*4>>>(A, g2cw, g2cb, POOL);

    // head
    k_fc<1024,1024,1><<<dim3(1024/256, BB), 256>>>(POOL, c4w, c4b, Y);
    k_fc<1024,512,0><<<dim3(512/256, BB), 256>>>(Y, c5w, c5b, out);
}

// round 4
// speedup vs baseline: 1.0960x; 1.0960x over previous
#include <cuda_runtime.h>
#include <math.h>
#include <stdint.h>

#define BB 16
#define NN 2048
#define KK 16
#define NPTS (BB*NN)   // 32768

// ---------------- scratch (device globals; no allocation allowed) ----------------
__device__ float gA[NPTS*128];
__device__ float gB[NPTS*128];
__device__ int   gIdx[NPTS*KK];
__device__ float gSq[NPTS];
__device__ float gPool[BB*1024];
__device__ float gY[BB*1024];

__device__ __forceinline__ void atomicMaxF(float* addr, float val){
    int old = __float_as_int(*addr);
    while (__int_as_float(old) < val) {
        int prev = atomicCAS((int*)addr, old, __float_as_int(val));
        if (prev == old) break;
        old = prev;
    }
}

// ---------------- squared norms: one warp per row ----------------
__global__ void k_sq(const float* __restrict__ H, float* __restrict__ SQ, int C){
    int gt = blockIdx.x*blockDim.x + threadIdx.x;
    int row = gt >> 5;
    int lane = gt & 31;
    if (row >= NPTS) return;
    const float* p = H + (size_t)row*C;
    float s = 0.f;
    for (int c = lane; c < C; c += 32) { float v = p[c]; s = fmaf(v,v,s); }
    #pragma unroll
    for (int o=16;o>0;o>>=1) s += __shfl_down_sync(0xffffffffu, s, o);
    if (lane==0) SQ[row] = s;
}

// ---------------- kNN: tiled distance + fused top-16 ----------------
// grid (N/128, B), 256 threads. d(i,j) = sq_i + sq_j - 2*dot(h_i,h_j).
// Thread (tx,ty) owns rows ty*8..+7, cols tx*8..+7 (contiguous -> float4 LDS).
// Per-dot accumulation order is c = 0..C-1 sequential (bit-identical to R2).
template<int C>
__global__ __launch_bounds__(256,1) void k_knn(const float* __restrict__ H,
                                               const float* __restrict__ SQ,
                                               int* __restrict__ IDX){
    constexpr int CHUNK = (C < 32) ? C : 32;
    constexpr int NC = C / CHUNK;
    constexpr int FILL = 128*CHUNK;               // elements per chunk tile
    constexpr int PRE  = (FILL + 255) / 256;      // ceil: per-thread fill quota
    extern __shared__ float sm[];
    float* sA   = sm;                    // [C][132] transposed i-tile
    float* sB   = sA + C*132;            // [2][CHUNK][132] double-buffered j-chunk
    float* sD   = sB + 2*CHUNK*132;      // [128][132] distance/dot tile
    float* sSqB = sD + 128*132;          // [128]
    float* topd = sSqB + 128;            // [128][17]
    int*   topi = (int*)(topd + 128*17); // [128][17]

    const int t  = threadIdx.x;
    const int tx = t & 15, ty = t >> 4;
    const int b  = blockIdx.y;
    const int i0 = blockIdx.x * 128;
    const size_t baseRow = (size_t)b * NN;

    for (int e = t; e < 128*C; e += 256) {
        int i = e / C, c = e - i*C;
        sA[c*132 + i] = H[(baseRow + i0 + i)*(size_t)C + c];
    }
    for (int e = t; e < 128*16; e += 256) {
        int i = e >> 4, s = e & 15;
        topd[i*17+s] = INFINITY;
        topi[i*17+s] = 0;
    }
    float sqa = (t < 128) ? SQ[baseRow + i0 + t] : 0.f;

    for (int jt = 0; jt < NN/128; ++jt) {
        __syncthreads();                   // prev scan done: sSqB/sD/sB[0] reusable
        const int j0 = jt*128;
        if (t < 128) sSqB[t] = SQ[baseRow + j0 + t];

        // fill chunk 0 into buffer 0 (full coverage incl. remainder)
        #pragma unroll
        for (int q = 0; q < PRE; ++q) {
            int e = t + q*256;
            if (e < FILL) {
                int j = e / CHUNK, c = e - (e/CHUNK)*CHUNK;
                sB[c*132 + j] = H[(baseRow + j0 + j)*(size_t)C + c];
            }
        }

        float acc[8][8];
        #pragma unroll
        for (int a=0;a<8;a++)
            #pragma unroll
            for (int c=0;c<8;c++) acc[a][c]=0.f;

        for (int ch = 0; ch < NC; ++ch) {
            __syncthreads();
            // prefetch next chunk into registers (latency hidden behind FMAs)
            float pre[PRE];
            if (ch + 1 < NC) {
                const int c0n = (ch+1)*CHUNK;
                #pragma unroll
                for (int q = 0; q < PRE; ++q) {
                    int e = t + q*256;
                    if (e < FILL) {
                        int j = e / CHUNK, c = e - (e/CHUNK)*CHUNK;
                        pre[q] = H[(baseRow + j0 + j)*(size_t)C + c0n + c];
                    }
                }
            }
            const float* aBase = sA + ch*CHUNK*132 + ty*8;
            const float* bBase = sB + (ch & 1)*CHUNK*132 + tx*8;
            #pragma unroll
            for (int cc = 0; cc < CHUNK; ++cc) {
                float4 a0 = *(const float4*)(aBase + cc*132);
                float4 a1 = *(const float4*)(aBase + cc*132 + 4);
                float4 b0 = *(const float4*)(bBase + cc*132);
                float4 b1 = *(const float4*)(bBase + cc*132 + 4);
                float av[8] = {a0.x,a0.y,a0.z,a0.w,a1.x,a1.y,a1.z,a1.w};
                float bv[8] = {b0.x,b0.y,b0.z,b0.w,b1.x,b1.y,b1.z,b1.w};
                #pragma unroll
                for (int ri=0;ri<8;ri++)
                    #pragma unroll
                    for (int rj=0;rj<8;rj++)
                        acc[ri][rj] = fmaf(av[ri], bv[rj], acc[ri][rj]);
            }
            if (ch + 1 < NC) {
                float* dst = sB + ((ch+1) & 1)*CHUNK*132;
                #pragma unroll
                for (int q = 0; q < PRE; ++q) {
                    int e = t + q*256;
                    if (e < FILL) {
                        int j = e / CHUNK, c = e - (e/CHUNK)*CHUNK;
                        dst[c*132 + j] = pre[q];
                    }
                }
            }
        }
        // write dot tile (exclusive 8x8 region per thread, float4 stores)
        #pragma unroll
        for (int ri=0;ri<8;ri++){
            *(float4*)(sD + (ty*8+ri)*132 + tx*8)     = make_float4(acc[ri][0],acc[ri][1],acc[ri][2],acc[ri][3]);
            *(float4*)(sD + (ty*8+ri)*132 + tx*8 + 4) = make_float4(acc[ri][4],acc[ri][5],acc[ri][6],acc[ri][7]);
        }
        __syncthreads();

        if (t < 128) {
            float* td = topd + t*17;
            int*   ti = topi + t*17;
            const float* drow = sD + t*132;
            float worst = td[15];
            #pragma unroll 4
            for (int jj = 0; jj < 128; ++jj) {
                float d = sqa + sSqB[jj] - 2.f*drow[jj];
                if (d < worst) {
                    int pos = 15;
                    while (pos > 0 && td[pos-1] > d) {
                        td[pos] = td[pos-1];
                        ti[pos] = ti[pos-1];
                        --pos;
                    }
                    td[pos] = d;
                    ti[pos] = j0 + jj;
                    worst = td[15];
                }
            }
        }
    }
    __syncthreads();
    if (t < 128) {
        int* o = IDX + (baseRow + i0 + t)*KK;
        #pragma unroll
        for (int s=0;s<16;s++) o[s] = topi[t*17+s];
    }
}

// ---------------- cov features: [x, cov(knn xyz).flatten(9)] -> 12 ch ----------------
__global__ void k_cov(const float* __restrict__ X, const int* __restrict__ IDX,
                      float* __restrict__ OUT){
    int p = blockIdx.x*blockDim.x + threadIdx.x;
    if (p >= NPTS) return;
    int b = p >> 11;
    const int* id = IDX + (size_t)p*KK;
    float px[16], py[16], pz[16];
    float mx=0.f,my=0.f,mz=0.f;
    #pragma unroll
    for (int k=0;k<16;k++){
        int j = id[k];
        const float* q = X + ((size_t)(b<<11) + j)*3;
        px[k]=q[0]; py[k]=q[1]; pz[k]=q[2];
        mx+=px[k]; my+=py[k]; mz+=pz[k];
    }
    mx *= (1.f/16.f); my *= (1.f/16.f); mz *= (1.f/16.f);
    float c00=0,c01=0,c02=0,c11=0,c12=0,c22=0;
    #pragma unroll
    for (int k=0;k<16;k++){
        float cx=px[k]-mx, cy=py[k]-my, cz=pz[k]-mz;
        c00=fmaf(cx,cx,c00); c01=fmaf(cx,cy,c01); c02=fmaf(cx,cz,c02);
        c11=fmaf(cy,cy,c11); c12=fmaf(cy,cz,c12); c22=fmaf(cz,cz,c22);
    }
    const float* xi = X + (size_t)p*3;
    float* o = OUT + (size_t)p*12;
    o[0]=xi[0]; o[1]=xi[1]; o[2]=xi[2];
    o[3]=c00; o[4]=c01; o[5]=c02;
    o[6]=c01; o[7]=c11; o[8]=c12;
    o[9]=c02; o[10]=c12; o[11]=c22;
}

// ---------------- pointwise dense (kernel_size=1 conv), optional BN+ReLU ----------------
template<int CIN,int COUT,int RELU,int BN>
__global__ __launch_bounds__(256) void k_dense(const float* __restrict__ X,
        const float* __restrict__ W, const float* __restrict__ bias,
        const float* __restrict__ bg, const float* __restrict__ bb,
        const float* __restrict__ bm, const float* __restrict__ bv,
        float* __restrict__ OUT){
    extern __shared__ float sm[];
    float* Xs = sm;                  // [64][CIN+1]
    float* Ws = Xs + 64*(CIN+1);     // [CIN][COUT]
    const int t = threadIdx.x;
    const size_t row0 = (size_t)blockIdx.x * 64;
    for (int e = t; e < 64*CIN; e += 256) {
        int r = e / CIN, k = e - r*CIN;
        Xs[r*(CIN+1)+k] = X[row0*CIN + e];
    }
    for (int e = t; e < CIN*COUT; e += 256) Ws[e] = W[e];
    __syncthreads();
    constexpr int CQ = COUT/4;
    for (int q = t; q < 32*CQ; q += 256) {
        int rp = q / CQ;
        int c4 = (q - rp*CQ)*4;
        float4 b4 = *(const float4*)(bias + c4);
        float a0[4] = {b4.x,b4.y,b4.z,b4.w};
        float a1[4] = {b4.x,b4.y,b4.z,b4.w};
        #pragma unroll 8
        for (int k=0;k<CIN;k++){
            float x0 = Xs[rp*(CIN+1)+k];
            float x1 = Xs[(rp+32)*(CIN+1)+k];
            float4 w = *(const float4*)(Ws + k*COUT + c4);
            a0[0]=fmaf(x0,w.x,a0[0]); a0[1]=fmaf(x0,w.y,a0[1]);
            a0[2]=fmaf(x0,w.z,a0[2]); a0[3]=fmaf(x0,w.w,a0[3]);
            a1[0]=fmaf(x1,w.x,a1[0]); a1[1]=fmaf(x1,w.y,a1[1]);
            a1[2]=fmaf(x1,w.z,a1[2]); a1[3]=fmaf(x1,w.w,a1[3]);
        }
        #pragma unroll
        for (int u=0;u<4;u++){
            float v0=a0[u], v1=a1[u];
            if (BN){
                int c = c4+u;
                float s   = bg[c]*rsqrtf(bv[c]+1e-3f);
                float off = bb[c] - bm[c]*s;
                v0 = fmaf(v0,s,off); v1 = fmaf(v1,s,off);
            }
            if (RELU){ v0=fmaxf(v0,0.f); v1=fmaxf(v1,0.f); }
            a0[u]=v0; a1[u]=v1;
        }
        *(float4*)(OUT + (row0+rp)*COUT + c4)    = make_float4(a0[0],a0[1],a0[2],a0[3]);
        *(float4*)(OUT + (row0+rp+32)*COUT + c4) = make_float4(a1[0],a1[1],a1[2],a1[3]);
    }
}

// ---------------- gather neighbors + max over k ----------------
template<int C>
__global__ void k_gmax(const float* __restrict__ H, const int* __restrict__ IDX,
                       float* __restrict__ OUT){
    constexpr int CQ = C/4;
    int e = blockIdx.x*blockDim.x + threadIdx.x;
    if (e >= NPTS*CQ) return;
    int p = e / CQ, c4 = (e - p*CQ)*4;
    int b = p >> 11;
    const int* id = IDX + (size_t)p*KK;
    float4 m = make_float4(-INFINITY,-INFINITY,-INFINITY,-INFINITY);
    #pragma unroll
    for (int k=0;k<16;k++){
        int j = id[k];
        float4 v = *(const float4*)(H + ((size_t)(b<<11)+j)*C + c4);
        m.x=fmaxf(m.x,v.x); m.y=fmaxf(m.y,v.y);
        m.z=fmaxf(m.z,v.z); m.w=fmaxf(m.w,v.w);
    }
    *(float4*)(OUT + (size_t)p*C + c4) = m;
}

// ---------------- 128->1024 GEMM fused with bias + global max over N ----------------
// grid (1024/128, N/128, B); 256 threads; contiguous 8x8 micro-tiles, float4 LDS.
__global__ __launch_bounds__(256,1) void k_gemm_pool(const float* __restrict__ X,
        const float* __restrict__ W, const float* __restrict__ bias,
        float* __restrict__ pool){
    extern __shared__ float sm[];
    float* XsT  = sm;              // [128 k][132 i]
    float* Ws   = XsT + 128*132;   // [128 k][132 c]
    float* sred = Ws  + 128*132;   // [128 c][17]
    const int t = threadIdx.x, tx = t & 15, ty = t >> 4;
    const int b = blockIdx.z;
    const size_t row0 = (size_t)b*NN + (size_t)blockIdx.y*128;
    const int c0 = blockIdx.x*128;

    for (int e=t; e<128*128; e+=256){
        int i = e >> 7, k = e & 127;
        XsT[k*132+i] = X[row0*128 + e];
    }
    for (int e=t; e<128*128; e+=256){
        int k = e >> 7, c = e & 127;
        Ws[k*132+c] = W[(size_t)k*1024 + c0 + c];
    }
    __syncthreads();

    float acc[8][8];
    #pragma unroll
    for (int a=0;a<8;a++)
        #pragma unroll
        for (int c=0;c<8;c++) acc[a][c]=0.f;

    const float* aBase = XsT + ty*8;
    const float* wBase = Ws  + tx*8;
    #pragma unroll 8
    for (int k=0;k<128;k++){
        float4 a0 = *(const float4*)(aBase + k*132);
        float4 a1 = *(const float4*)(aBase + k*132 + 4);
        float4 w0 = *(const float4*)(wBase + k*132);
        float4 w1 = *(const float4*)(wBase + k*132 + 4);
        float av[8] = {a0.x,a0.y,a0.z,a0.w,a1.x,a1.y,a1.z,a1.w};
        float wv[8] = {w0.x,w0.y,w0.z,w0.w,w1.x,w1.y,w1.z,w1.w};
        #pragma unroll
        for (int ri=0;ri<8;ri++)
            #pragma unroll
            for (int rj=0;rj<8;rj++)
                acc[ri][rj] = fmaf(av[ri], wv[rj], acc[ri][rj]);
    }
    // rows = ty*8+ri, cols = tx*8+rj: reduce max over rows per column
    #pragma unroll
    for (int rj=0;rj<8;rj++){
        float m = acc[0][rj];
        #pragma unroll
        for (int ri=1;ri<8;ri++) m = fmaxf(m, acc[ri][rj]);
        sred[(tx*8+rj)*17 + ty] = m;
    }
    __syncthreads();
    if (t < 128){
        float m = sred[t*17];
        #pragma unroll
        for (int q=1;q<16;q++) m = fmaxf(m, sred[t*17+q]);
        m += bias[c0 + t];
        atomicMaxF(&pool[b*1024 + c0 + t], m);
    }
}

__global__ void k_init(float* __restrict__ p, int n){
    int e = blockIdx.x*blockDim.x + threadIdx.x;
    if (e < n) p[e] = -INFINITY;
}

// ---------------- tiny FC layers over pooled [B, CIN] ----------------
template<int CIN,int COUT,int RELU>
__global__ __launch_bounds__(256) void k_fc(const float* __restrict__ IN,
        const float* __restrict__ W, const float* __restrict__ bias,
        float* __restrict__ OUT){
    __shared__ float Ps[CIN];
    const int t = threadIdx.x;
    const int b = blockIdx.y;
    const int c = blockIdx.x*256 + t;
    for (int e=t;e<CIN;e+=256) Ps[e]=IN[b*CIN+e];
    __syncthreads();
    float acc = bias[c];
    #pragma unroll 8
    for (int k=0;k<CIN;k++) acc = fmaf(Ps[k], W[(size_t)k*COUT + c], acc);
    if (RELU) acc = fmaxf(acc, 0.f);
    OUT[b*COUT + c] = acc;
}

// ---------------- host ----------------
static inline int knn_smem(int C){
    int ch = C < 32 ? C : 32;
    return (C*132 + 2*ch*132 + 128*132 + 128 + 128*17 + 128*17)*4;
}
static inline int dense_smem(int cin, int cout){
    return (64*(cin+1) + cin*cout)*4;
}
#define GEMM_SMEM ((128*132*2 + 128*17)*4)

extern "C" void kernel_launch(void* const* d_in, const int* in_sizes, int n_in,
                              void* d_out, int out_size){
    const float* x    = (const float*)d_in[0];
    const float* c1w  = (const float*)d_in[1];
    const float* c1b  = (const float*)d_in[2];
    const float* c2w  = (const float*)d_in[3];
    const float* c2b  = (const float*)d_in[4];
    const float* c3w  = (const float*)d_in[5];
    const float* c3b  = (const float*)d_in[6];
    const float* g1lw = (const float*)d_in[7];
    const float* g1lb = (const float*)d_in[8];
    const float* g1cw = (const float*)d_in[9];
    const float* g1cb = (const float*)d_in[10];
    const float* g2lw = (const float*)d_in[11];
    const float* g2lb = (const float*)d_in[12];
    const float* g2cw = (const float*)d_in[13];
    const float* g2cb = (const float*)d_in[14];
    const float* c4w  = (const float*)d_in[15];
    const float* c4b  = (const float*)d_in[16];
    const float* c5w  = (const float*)d_in[17];
    const float* c5b  = (const float*)d_in[18];
    const float* bn1g = (const float*)d_in[19];
    const float* bn1b = (const float*)d_in[20];
    const float* bn1m = (const float*)d_in[21];
    const float* bn1v = (const float*)d_in[22];
    const float* bn2g = (const float*)d_in[23];
    const float* bn2b = (const float*)d_in[24];
    const float* bn2m = (const float*)d_in[25];
    const float* bn2v = (const float*)d_in[26];
    const float* bn3g = (const float*)d_in[27];
    const float* bn3b = (const float*)d_in[28];
    const float* bn3m = (const float*)d_in[29];
    const float* bn3v = (const float*)d_in[30];
    float* out = (float*)d_out;

    float *A,*B,*SQ,*POOL,*Y; int* ID;
    cudaGetSymbolAddress((void**)&A, gA);
    cudaGetSymbolAddress((void**)&B, gB);
    cudaGetSymbolAddress((void**)&SQ, gSq);
    cudaGetSymbolAddress((void**)&POOL, gPool);
    cudaGetSymbolAddress((void**)&Y, gY);
    cudaGetSymbolAddress((void**)&ID, gIdx);

    cudaFuncSetAttribute(k_knn<3>,   cudaFuncAttributeMaxDynamicSharedMemorySize, knn_smem(3));
    cudaFuncSetAttribute(k_knn<64>,  cudaFuncAttributeMaxDynamicSharedMemorySize, knn_smem(64));
    cudaFuncSetAttribute(k_knn<128>, cudaFuncAttributeMaxDynamicSharedMemorySize, knn_smem(128));
    cudaFuncSetAttribute(k_gemm_pool, cudaFuncAttributeMaxDynamicSharedMemorySize, GEMM_SMEM);
    cudaFuncSetAttribute((void*)k_dense<64,128,1,0>, cudaFuncAttributeMaxDynamicSharedMemorySize,
                         dense_smem(64,128));
    cudaFuncSetAttribute((void*)k_dense<128,128,0,0>, cudaFuncAttributeMaxDynamicSharedMemorySize,
                         dense_smem(128,128));

    const dim3 knnGrid(NN/128, BB);

    // stage 0: knn on xyz + covariance features
    k_sq<<<(NPTS*32)/256, 256>>>(x, SQ, 3);
    k_knn<3><<<knnGrid, 256, knn_smem(3)>>>(x, SQ, ID);
    k_cov<<<NPTS/256, 256>>>(x, ID, A);                       // A: [*,12]

    // MLP stack with BN+ReLU
    k_dense<12,12,1,1><<<NPTS/64, 256, dense_smem(12,12)>>>(A, c1w, c1b, bn1g,bn1b,bn1m,bn1v, B);
    k_dense<12,64,1,1><<<NPTS/64, 256, dense_smem(12,64)>>>(B, c2w, c2b, bn2g,bn2b,bn2m,bn2v, A);
    k_dense<64,64,1,1><<<NPTS/64, 256, dense_smem(64,64)>>>(A, c3w, c3b, bn3g,bn3b,bn3m,bn3v, B); // h64 in B

    // graph layer 1 (C=64 -> 128, relu)
    k_sq<<<(NPTS*32)/256, 256>>>(B, SQ, 64);
    k_knn<64><<<knnGrid, 256, knn_smem(64)>>>(B, SQ, ID);
    k_gmax<64><<<(NPTS*16)/256, 256>>>(B, ID, A);
    k_dense<64,64,0,0><<<NPTS/64, 256, dense_smem(64,64)>>>(A, g1lw, g1lb, 0,0,0,0, B);
    k_dense<64,128,1,0><<<NPTS/64, 256, dense_smem(64,128)>>>(B, g1cw, g1cb, 0,0,0,0, A); // h128 in A

    // graph layer 2 (C=128 -> 1024, no relu) fused with global max pool
    k_sq<<<(NPTS*32)/256, 256>>>(A, SQ, 128);
    k_knn<128><<<knnGrid, 256, knn_smem(128)>>>(A, SQ, ID);
    k_gmax<128><<<(NPTS*32)/256, 256>>>(A, ID, B);
    k_dense<128,128,0,0><<<NPTS/64, 256, dense_smem(128,128)>>>(B, g2lw, g2lb, 0,0,0,0, A);
    k_init<<<(BB*1024)/256, 256>>>(POOL, BB*1024);
    k_gemm_pool<<<dim3(1024/128, NN/128, BB), 256, GEMM_SMEM>>>(A, g2cw, g2cb, POOL);

    // head
    k_fc<1024,1024,1><<<dim3(1024/256, BB), 256>>>(POOL, c4w, c4b, Y);
    k_fc<1024,512,0><<<dim3(512/256, BB), 256>>>(Y, c5w, c5b, out);
}

// round 5
// speedup vs baseline: 1.3854x; 1.2641x over previous
#include <cuda_runtime.h>
#include <math.h>
#include <stdint.h>

#define BB 16
#define NN 2048
#define KK 16
#define NPTS (BB*NN)   // 32768

// ---------------- scratch (device globals; no allocation allowed) ----------------
__device__ float gA[NPTS*128];
__device__ float gB[NPTS*128];
__device__ int   gIdx[NPTS*KK];
__device__ float gSq[NPTS];
__device__ float gPool[BB*1024];
__device__ float gY[BB*1024];

__device__ __forceinline__ void atomicMaxF(float* addr, float val){
    int old = __float_as_int(*addr);
    while (__int_as_float(old) < val) {
        int prev = atomicCAS((int*)addr, old, __float_as_int(val));
        if (prev == old) break;
        old = prev;
    }
}

// ---------------- squared norms: one warp per row ----------------
__global__ void k_sq(const float* __restrict__ H, float* __restrict__ SQ, int C){
    int gt = blockIdx.x*blockDim.x + threadIdx.x;
    int row = gt >> 5;
    int lane = gt & 31;
    if (row >= NPTS) return;
    const float* p = H + (size_t)row*C;
    float s = 0.f;
    for (int c = lane; c < C; c += 32) { float v = p[c]; s = fmaf(v,v,s); }
    #pragma unroll
    for (int o=16;o>0;o>>=1) s += __shfl_down_sync(0xffffffffu, s, o);
    if (lane==0) SQ[row] = s;
}

// ---------------- kNN: tiled distance + fused top-16 ----------------
// grid (N/128, B), 256 threads, 2 CTAs/SM. 128i x 64j tiles, 8x4 micro-tiles.
// d(i,j) = sq_i + sq_j - 2*dot. Dot accumulation c-sequential (bit-identical
// to prior passing kernels); scan visits j ascending with stable insertion.
template<int C>
__global__ __launch_bounds__(256,2) void k_knn(const float* __restrict__ H,
                                               const float* __restrict__ SQ,
                                               int* __restrict__ IDX){
    constexpr int CHUNK = (C < 32) ? C : 32;
    constexpr int NC = C / CHUNK;
    constexpr bool ACH = (C > 64);               // chunk+double-buffer A tile
    constexpr int JT = 64;
    constexpr int FILL_B = JT*CHUNK;
    constexpr int PRE_B  = (FILL_B + 255)/256;
    constexpr int FILL_A = 128*CHUNK;
    constexpr int PRE_A  = ACH ? (FILL_A + 255)/256 : 1;
    constexpr int SA_FLOATS = ACH ? 2*32*132 : C*132;

    extern __shared__ float sm[];
    float* sA   = sm;                     // ACH ? [2][32][132] : [C][132]
    float* sB   = sA + SA_FLOATS;         // [2][CHUNK][68]
    float* sD   = sB + 2*CHUNK*68;        // [128][68]
    float* sSqB = sD + 128*68;            // [64]
    float* topd = sSqB + 64;              // [128][17]
    int*   topi = (int*)(topd + 128*17);  // [128][17]

    const int t  = threadIdx.x;
    const int tx = t & 15, ty = t >> 4;
    const int b  = blockIdx.y;
    const int i0 = blockIdx.x * 128;
    const size_t baseRow = (size_t)b * NN;

    if (!ACH) {
        for (int e = t; e < 128*C; e += 256) {
            int i = e / C, c = e - i*C;
            sA[c*132 + i] = H[(baseRow + i0 + i)*(size_t)C + c];
        }
    }
    for (int e = t; e < 128*16; e += 256) {
        int i = e >> 4, s = e & 15;
        topd[i*17+s] = INFINITY;
        topi[i*17+s] = 0;
    }
    float sqa = (t < 128) ? SQ[baseRow + i0 + t] : 0.f;

    for (int jt = 0; jt < NN/JT; ++jt) {
        __syncthreads();                  // prev scan done; buffers reusable
        const int j0 = jt*JT;
        if (t < JT) sSqB[t] = SQ[baseRow + j0 + t];

        // fill B chunk 0
        #pragma unroll
        for (int q = 0; q < PRE_B; ++q) {
            int e = t + q*256;
            if (e < FILL_B) {
                int j = e / CHUNK, c = e - (e/CHUNK)*CHUNK;
                sB[c*68 + j] = H[(baseRow + j0 + j)*(size_t)C + c];
            }
        }
        // fill A chunk 0 (chunked path only; FILL_A = PRE_A*256 exactly)
        if (ACH) {
            #pragma unroll
            for (int q = 0; q < PRE_A; ++q) {
                int e = t + q*256;
                int i = e >> 5, c = e & 31;
                sA[c*132 + i] = H[(baseRow + i0 + i)*(size_t)C + c];
            }
        }

        float acc[8][4];
        #pragma unroll
        for (int a=0;a<8;a++)
            #pragma unroll
            for (int c=0;c<4;c++) acc[a][c]=0.f;

        for (int ch = 0; ch < NC; ++ch) {
            __syncthreads();
            float preB[PRE_B];
            float preA[PRE_A];
            if (NC > 1 && ch + 1 < NC) {
                const int c0n = (ch+1)*CHUNK;
                #pragma unroll
                for (int q = 0; q < PRE_B; ++q) {
                    int e = t + q*256;
                    if (e < FILL_B) {
                        int j = e / CHUNK, c = e - (e/CHUNK)*CHUNK;
                        preB[q] = H[(baseRow + j0 + j)*(size_t)C + c0n + c];
                    }
                }
                if (ACH) {
                    #pragma unroll
                    for (int q = 0; q < PRE_A; ++q) {
                        int e = t + q*256;
                        int i = e >> 5, c = e & 31;
                        preA[q] = H[(baseRow + i0 + i)*(size_t)C + c0n + c];
                    }
                }
            }
            const float* aBase = (ACH ? sA + (ch & 1)*(32*132)
                                      : sA + ch*CHUNK*132) + ty*8;
            const float* bBase = sB + (ch & 1)*(CHUNK*68) + tx*4;
            #pragma unroll
            for (int cc = 0; cc < CHUNK; ++cc) {
                float4 a0 = *(const float4*)(aBase + cc*132);
                float4 a1 = *(const float4*)(aBase + cc*132 + 4);
                float4 b0 = *(const float4*)(bBase + cc*68);
                float av[8] = {a0.x,a0.y,a0.z,a0.w,a1.x,a1.y,a1.z,a1.w};
                float bv[4] = {b0.x,b0.y,b0.z,b0.w};
                #pragma unroll
                for (int ri=0;ri<8;ri++)
                    #pragma unroll
                    for (int rj=0;rj<4;rj++)
                        acc[ri][rj] = fmaf(av[ri], bv[rj], acc[ri][rj]);
            }
            if (NC > 1 && ch + 1 < NC) {
                float* dB = sB + ((ch+1) & 1)*(CHUNK*68);
                #pragma unroll
                for (int q = 0; q < PRE_B; ++q) {
                    int e = t + q*256;
                    if (e < FILL_B) {
                        int j = e / CHUNK, c = e - (e/CHUNK)*CHUNK;
                        dB[c*68 + j] = preB[q];
                    }
                }
                if (ACH) {
                    float* dA = sA + ((ch+1) & 1)*(32*132);
                    #pragma unroll
                    for (int q = 0; q < PRE_A; ++q) {
                        int e = t + q*256;
                        int i = e >> 5, c = e & 31;
                        dA[c*132 + i] = preA[q];
                    }
                }
            }
        }
        // write dot tile (exclusive 8x4 region per thread)
        #pragma unroll
        for (int ri=0;ri<8;ri++)
            *(float4*)(sD + (ty*8+ri)*68 + tx*4) =
                make_float4(acc[ri][0],acc[ri][1],acc[ri][2],acc[ri][3]);
        __syncthreads();

        if (t < 128) {
            float* td = topd + t*17;
            int*   ti = topi + t*17;
            const float* drow = sD + t*68;
            float worst = td[15];
            #pragma unroll 4
            for (int jj = 0; jj < JT; ++jj) {
                float d = sqa + sSqB[jj] - 2.f*drow[jj];
                if (d < worst) {
                    int pos = 15;
                    while (pos > 0 && td[pos-1] > d) {
                        td[pos] = td[pos-1];
                        ti[pos] = ti[pos-1];
                        --pos;
                    }
                    td[pos] = d;
                    ti[pos] = j0 + jj;
                    worst = td[15];
                }
            }
        }
    }
    __syncthreads();
    if (t < 128) {
        int* o = IDX + (baseRow + i0 + t)*KK;
        #pragma unroll
        for (int s=0;s<16;s++) o[s] = topi[t*17+s];
    }
}

// ---------------- cov features: [x, cov(knn xyz).flatten(9)] -> 12 ch ----------------
__global__ void k_cov(const float* __restrict__ X, const int* __restrict__ IDX,
                      float* __restrict__ OUT){
    int p = blockIdx.x*blockDim.x + threadIdx.x;
    if (p >= NPTS) return;
    int b = p >> 11;
    const int* id = IDX + (size_t)p*KK;
    float px[16], py[16], pz[16];
    float mx=0.f,my=0.f,mz=0.f;
    #pragma unroll
    for (int k=0;k<16;k++){
        int j = id[k];
        const float* q = X + ((size_t)(b<<11) + j)*3;
        px[k]=q[0]; py[k]=q[1]; pz[k]=q[2];
        mx+=px[k]; my+=py[k]; mz+=pz[k];
    }
    mx *= (1.f/16.f); my *= (1.f/16.f); mz *= (1.f/16.f);
    float c00=0,c01=0,c02=0,c11=0,c12=0,c22=0;
    #pragma unroll
    for (int k=0;k<16;k++){
        float cx=px[k]-mx, cy=py[k]-my, cz=pz[k]-mz;
        c00=fmaf(cx,cx,c00); c01=fmaf(cx,cy,c01); c02=fmaf(cx,cz,c02);
        c11=fmaf(cy,cy,c11); c12=fmaf(cy,cz,c12); c22=fmaf(cz,cz,c22);
    }
    const float* xi = X + (size_t)p*3;
    float* o = OUT + (size_t)p*12;
    o[0]=xi[0]; o[1]=xi[1]; o[2]=xi[2];
    o[3]=c00; o[4]=c01; o[5]=c02;
    o[6]=c01; o[7]=c11; o[8]=c12;
    o[9]=c02; o[10]=c12; o[11]=c22;
}

// ---------------- pointwise dense (kernel_size=1 conv), optional BN+ReLU ----------------
template<int CIN,int COUT,int RELU,int BN>
__global__ __launch_bounds__(256) void k_dense(const float* __restrict__ X,
        const float* __restrict__ W, const float* __restrict__ bias,
        const float* __restrict__ bg, const float* __restrict__ bb,
        const float* __restrict__ bm, const float* __restrict__ bv,
        float* __restrict__ OUT){
    extern __shared__ float sm[];
    float* Xs = sm;                  // [64][CIN+1]
    float* Ws = Xs + 64*(CIN+1);     // [CIN][COUT]
    const int t = threadIdx.x;
    const size_t row0 = (size_t)blockIdx.x * 64;
    for (int e = t; e < 64*CIN; e += 256) {
        int r = e / CIN, k = e - r*CIN;
        Xs[r*(CIN+1)+k] = X[row0*CIN + e];
    }
    for (int e = t; e < CIN*COUT; e += 256) Ws[e] = W[e];
    __syncthreads();
    constexpr int CQ = COUT/4;
    for (int q = t; q < 32*CQ; q += 256) {
        int rp = q / CQ;
        int c4 = (q - rp*CQ)*4;
        float4 b4 = *(const float4*)(bias + c4);
        float a0[4] = {b4.x,b4.y,b4.z,b4.w};
        float a1[4] = {b4.x,b4.y,b4.z,b4.w};
        #pragma unroll 8
        for (int k=0;k<CIN;k++){
            float x0 = Xs[rp*(CIN+1)+k];
            float x1 = Xs[(rp+32)*(CIN+1)+k];
            float4 w = *(const float4*)(Ws + k*COUT + c4);
            a0[0]=fmaf(x0,w.x,a0[0]); a0[1]=fmaf(x0,w.y,a0[1]);
            a0[2]=fmaf(x0,w.z,a0[2]); a0[3]=fmaf(x0,w.w,a0[3]);
            a1[0]=fmaf(x1,w.x,a1[0]); a1[1]=fmaf(x1,w.y,a1[1]);
            a1[2]=fmaf(x1,w.z,a1[2]); a1[3]=fmaf(x1,w.w,a1[3]);
        }
        #pragma unroll
        for (int u=0;u<4;u++){
            float v0=a0[u], v1=a1[u];
            if (BN){
                int c = c4+u;
                float s   = bg[c]*rsqrtf(bv[c]+1e-3f);
                float off = bb[c] - bm[c]*s;
                v0 = fmaf(v0,s,off); v1 = fmaf(v1,s,off);
            }
            if (RELU){ v0=fmaxf(v0,0.f); v1=fmaxf(v1,0.f); }
            a0[u]=v0; a1[u]=v1;
        }
        *(float4*)(OUT + (row0+rp)*COUT + c4)    = make_float4(a0[0],a0[1],a0[2],a0[3]);
        *(float4*)(OUT + (row0+rp+32)*COUT + c4) = make_float4(a1[0],a1[1],a1[2],a1[3]);
    }
}

// ---------------- gather neighbors + max over k ----------------
template<int C>
__global__ void k_gmax(const float* __restrict__ H, const int* __restrict__ IDX,
                       float* __restrict__ OUT){
    constexpr int CQ = C/4;
    int e = blockIdx.x*blockDim.x + threadIdx.x;
    if (e >= NPTS*CQ) return;
    int p = e / CQ, c4 = (e - p*CQ)*4;
    int b = p >> 11;
    const int* id = IDX + (size_t)p*KK;
    float4 m = make_float4(-INFINITY,-INFINITY,-INFINITY,-INFINITY);
    #pragma unroll
    for (int k=0;k<16;k++){
        int j = id[k];
        float4 v = *(const float4*)(H + ((size_t)(b<<11)+j)*C + c4);
        m.x=fmaxf(m.x,v.x); m.y=fmaxf(m.y,v.y);
        m.z=fmaxf(m.z,v.z); m.w=fmaxf(m.w,v.w);
    }
    *(float4*)(OUT + (size_t)p*C + c4) = m;
}

// ---------------- 128->1024 GEMM fused with bias + global max over N ----------------
// grid (1024/64, N/128, B); 256 threads, 2 CTAs/SM; 8x4 micro-tiles.
__global__ __launch_bounds__(256,2) void k_gemm_pool(const float* __restrict__ X,
        const float* __restrict__ W, const float* __restrict__ bias,
        float* __restrict__ pool){
    extern __shared__ float sm[];
    float* XsT  = sm;              // [128 k][132 i]
    float* Ws   = XsT + 128*132;   // [128 k][68 c]
    float* sred = Ws  + 128*68;    // [64 c][17]
    const int t = threadIdx.x, tx = t & 15, ty = t >> 4;
    const int b = blockIdx.z;
    const size_t row0 = (size_t)b*NN + (size_t)blockIdx.y*128;
    const int c0 = blockIdx.x*64;

    for (int e=t; e<128*128; e+=256){
        int i = e >> 7, k = e & 127;
        XsT[k*132+i] = X[row0*128 + e];
    }
    for (int e=t; e<128*64; e+=256){
        int k = e >> 6, c = e & 63;
        Ws[k*68+c] = W[(size_t)k*1024 + c0 + c];
    }
    __syncthreads();

    float acc[8][4];
    #pragma unroll
    for (int a=0;a<8;a++)
        #pragma unroll
        for (int c=0;c<4;c++) acc[a][c]=0.f;

    const float* aBase = XsT + ty*8;
    const float* wBase = Ws  + tx*4;
    #pragma unroll 8
    for (int k=0;k<128;k++){
        float4 a0 = *(const float4*)(aBase + k*132);
        float4 a1 = *(const float4*)(aBase + k*132 + 4);
        float4 w0 = *(const float4*)(wBase + k*68);
        float av[8] = {a0.x,a0.y,a0.z,a0.w,a1.x,a1.y,a1.z,a1.w};
        float wv[4] = {w0.x,w0.y,w0.z,w0.w};
        #pragma unroll
        for (int ri=0;ri<8;ri++)
            #pragma unroll
            for (int rj=0;rj<4;rj++)
                acc[ri][rj] = fmaf(av[ri], wv[rj], acc[ri][rj]);
    }
    // rows = ty*8+ri, cols = tx*4+rj: per-col max over this thread's 8 rows
    #pragma unroll
    for (int rj=0;rj<4;rj++){
        float m = acc[0][rj];
        #pragma unroll
        for (int ri=1;ri<8;ri++) m = fmaxf(m, acc[ri][rj]);
        sred[(tx*4+rj)*17 + ty] = m;
    }
    __syncthreads();
    if (t < 64){
        float m = sred[t*17];
        #pragma unroll
        for (int q=1;q<16;q++) m = fmaxf(m, sred[t*17+q]);
        m += bias[c0 + t];
        atomicMaxF(&pool[b*1024 + c0 + t], m);
    }
}

__global__ void k_init(float* __restrict__ p, int n){
    int e = blockIdx.x*blockDim.x + threadIdx.x;
    if (e < n) p[e] = -INFINITY;
}

// ---------------- tiny FC layers over pooled [B, CIN] ----------------
template<int CIN,int COUT,int RELU>
__global__ __launch_bounds__(256) void k_fc(const float* __restrict__ IN,
        const float* __restrict__ W, const float* __restrict__ bias,
        float* __restrict__ OUT){
    __shared__ float Ps[CIN];
    const int t = threadIdx.x;
    const int b = blockIdx.y;
    const int c = blockIdx.x*256 + t;
    for (int e=t;e<CIN;e+=256) Ps[e]=IN[b*CIN+e];
    __syncthreads();
    float acc = bias[c];
    #pragma unroll 8
    for (int k=0;k<CIN;k++) acc = fmaf(Ps[k], W[(size_t)k*COUT + c], acc);
    if (RELU) acc = fmaxf(acc, 0.f);
    OUT[b*COUT + c] = acc;
}

// ---------------- host ----------------
static inline int knn_smem(int C){
    int ch = C < 32 ? C : 32;
    int sa = (C > 64) ? 2*32*132 : C*132;
    return (sa + 2*ch*68 + 128*68 + 64 + 128*17 + 128*17)*4;
}
static inline int dense_smem(int cin, int cout){
    return (64*(cin+1) + cin*cout)*4;
}
#define GEMM_SMEM ((128*132 + 128*68 + 64*17)*4)

extern "C" void kernel_launch(void* const* d_in, const int* in_sizes, int n_in,
                              void* d_out, int out_size){
    const float* x    = (const float*)d_in[0];
    const float* c1w  = (const float*)d_in[1];
    const float* c1b  = (const float*)d_in[2];
    const float* c2w  = (const float*)d_in[3];
    const float* c2b  = (const float*)d_in[4];
    const float* c3w  = (const float*)d_in[5];
    const float* c3b  = (const float*)d_in[6];
    const float* g1lw = (const float*)d_in[7];
    const float* g1lb = (const float*)d_in[8];
    const float* g1cw = (const float*)d_in[9];
    const float* g1cb = (const float*)d_in[10];
    const float* g2lw = (const float*)d_in[11];
    const float* g2lb = (const float*)d_in[12];
    const float* g2cw = (const float*)d_in[13];
    const float* g2cb = (const float*)d_in[14];
    const float* c4w  = (const float*)d_in[15];
    const float* c4b  = (const float*)d_in[16];
    const float* c5w  = (const float*)d_in[17];
    const float* c5b  = (const float*)d_in[18];
    const float* bn1g = (const float*)d_in[19];
    const float* bn1b = (const float*)d_in[20];
    const float* bn1m = (const float*)d_in[21];
    const float* bn1v = (const float*)d_in[22];
    const float* bn2g = (const float*)d_in[23];
    const float* bn2b = (const float*)d_in[24];
    const float* bn2m = (const float*)d_in[25];
    const float* bn2v = (const float*)d_in[26];
    const float* bn3g = (const float*)d_in[27];
    const float* bn3b = (const float*)d_in[28];
    const float* bn3m = (const float*)d_in[29];
    const float* bn3v = (const float*)d_in[30];
    float* out = (float*)d_out;

    float *A,*B,*SQ,*POOL,*Y; int* ID;
    cudaGetSymbolAddress((void**)&A, gA);
    cudaGetSymbolAddress((void**)&B, gB);
    cudaGetSymbolAddress((void**)&SQ, gSq);
    cudaGetSymbolAddress((void**)&POOL, gPool);
    cudaGetSymbolAddress((void**)&Y, gY);
    cudaGetSymbolAddress((void**)&ID, gIdx);

    cudaFuncSetAttribute(k_knn<3>,   cudaFuncAttributeMaxDynamicSharedMemorySize, knn_smem(3));
    cudaFuncSetAttribute(k_knn<64>,  cudaFuncAttributeMaxDynamicSharedMemorySize, knn_smem(64));
    cudaFuncSetAttribute(k_knn<128>, cudaFuncAttributeMaxDynamicSharedMemorySize, knn_smem(128));
    cudaFuncSetAttribute(k_gemm_pool, cudaFuncAttributeMaxDynamicSharedMemorySize, GEMM_SMEM);
    cudaFuncSetAttribute((void*)k_dense<64,128,1,0>, cudaFuncAttributeMaxDynamicSharedMemorySize,
                         dense_smem(64,128));
    cudaFuncSetAttribute((void*)k_dense<128,128,0,0>, cudaFuncAttributeMaxDynamicSharedMemorySize,
                         dense_smem(128,128));

    const dim3 knnGrid(NN/128, BB);

    // stage 0: knn on xyz + covariance features
    k_sq<<<(NPTS*32)/256, 256>>>(x, SQ, 3);
    k_knn<3><<<knnGrid, 256, knn_smem(3)>>>(x, SQ, ID);
    k_cov<<<NPTS/256, 256>>>(x, ID, A);                       // A: [*,12]

    // MLP stack with BN+ReLU
    k_dense<12,12,1,1><<<NPTS/64, 256, dense_smem(12,12)>>>(A, c1w, c1b, bn1g,bn1b,bn1m,bn1v, B);
    k_dense<12,64,1,1><<<NPTS/64, 256, dense_smem(12,64)>>>(B, c2w, c2b, bn2g,bn2b,bn2m,bn2v, A);
    k_dense<64,64,1,1><<<NPTS/64, 256, dense_smem(64,64)>>>(A, c3w, c3b, bn3g,bn3b,bn3m,bn3v, B); // h64 in B

    // graph layer 1 (C=64 -> 128, relu)
    k_sq<<<(NPTS*32)/256, 256>>>(B, SQ, 64);
    k_knn<64><<<knnGrid, 256, knn_smem(64)>>>(B, SQ, ID);
    k_gmax<64><<<(NPTS*16)/256, 256>>>(B, ID, A);
    k_dense<64,64,0,0><<<NPTS/64, 256, dense_smem(64,64)>>>(A, g1lw, g1lb, 0,0,0,0, B);
    k_dense<64,128,1,0><<<NPTS/64, 256, dense_smem(64,128)>>>(B, g1cw, g1cb, 0,0,0,0, A); // h128 in A

    // graph layer 2 (C=128 -> 1024, no relu) fused with global max pool
    k_sq<<<(NPTS*32)/256, 256>>>(A, SQ, 128);
    k_knn<128><<<knnGrid, 256, knn_smem(128)>>>(A, SQ, ID);
    k_gmax<128><<<(NPTS*32)/256, 256>>>(A, ID, B);
    k_dense<128,128,0,0><<<NPTS/64, 256, dense_smem(128,128)>>>(B, g2lw, g2lb, 0,0,0,0, A);
    k_init<<<(BB*1024)/256, 256>>>(POOL, BB*1024);
    k_gemm_pool<<<dim3(1024/64, NN/128, BB), 256, GEMM_SMEM>>>(A, g2cw, g2cb, POOL);

    // head
    k_fc<1024,1024,1><<<dim3(1024/256, BB), 256>>>(POOL, c4w, c4b, Y);
    k_fc<1024,512,0><<<dim3(512/256, BB), 256>>>(Y, c5w, c5b, out);
}

// round 6
// speedup vs baseline: 1.8178x; 1.3121x over previous
#include <cuda_runtime.h>
#include <math.h>
#include <stdint.h>

#define BB 16
#define NN 2048
#define KK 16
#define NPTS (BB*NN)   // 32768

// ---------------- scratch (device globals; no allocation allowed) ----------------
__device__ float gA[NPTS*128];
__device__ float gB[NPTS*128];
__device__ int   gIdx[NPTS*KK];
__device__ float gSq[NPTS];
__device__ float gPool[BB*1024];
__device__ float gY[BB*1024];

__device__ __forceinline__ void atomicMaxF(float* addr, float val){
    int old = __float_as_int(*addr);
    while (__int_as_float(old) < val) {
        int prev = atomicCAS((int*)addr, old, __float_as_int(val));
        if (prev == old) break;
        old = prev;
    }
}

// ---------------- squared norms: one warp per row ----------------
__global__ void k_sq(const float* __restrict__ H, float* __restrict__ SQ, int C){
    int gt = blockIdx.x*blockDim.x + threadIdx.x;
    int row = gt >> 5;
    int lane = gt & 31;
    if (row >= NPTS) return;
    const float* p = H + (size_t)row*C;
    float s = 0.f;
    for (int c = lane; c < C; c += 32) { float v = p[c]; s = fmaf(v,v,s); }
    #pragma unroll
    for (int o=16;o>0;o>>=1) s += __shfl_down_sync(0xffffffffu, s, o);
    if (lane==0) SQ[row] = s;
}

// ---------------- kNN: tiled distance + register-resident top-16 ----------------
// grid (N/128, B), 256 threads, 2 CTAs/SM. 128i x 64j tiles, 8x4 micro-tiles.
// Thread t owns row t&127, j-half t>>7 (32 of 64 per tile): keeps a sorted
// 16-entry (d,idx) register list; final exact merge of the two halves.
// Dot accumulation is c-sequential per chunk (bit-identical to R5).
template<int C>
__global__ __launch_bounds__(256,2) void k_knn(const float* __restrict__ H,
                                               const float* __restrict__ SQ,
                                               int* __restrict__ IDX){
    constexpr int CHUNK = (C < 32) ? C : 32;
    constexpr int NC = C / CHUNK;
    constexpr bool ACH = (C > 64);       // chunk+double-buffer A tile
    constexpr bool VEC = (C >= 32);
    constexpr int JT = 64;
    constexpr int SA_FLOATS = ACH ? 2*32*132 : C*132;

    extern __shared__ float sm[];
    float* sA   = sm;                    // ACH ? [2][32][132] : [C][132]
    float* sB   = sA + SA_FLOATS;        // [2][CHUNK][68]
    float* sD   = sB + 2*CHUNK*68;       // [128][68] (reused as merge area)
    float* sSqB = sD + 128*68;           // [64]

    const int t  = threadIdx.x;
    const int tx = t & 15, ty = t >> 4;
    const int row = t & 127, half = t >> 7;
    const int b  = blockIdx.y;
    const int i0 = blockIdx.x * 128;
    const size_t baseRow = (size_t)b * NN;

    if (!ACH) {
        if (VEC) {
            #pragma unroll
            for (int q = 0; q < (128*(C/4))/256; ++q) {
                int i = t & 127;
                int c4 = (t >> 7) + q*2;
                float4 v = *(const float4*)&H[(baseRow + i0 + i)*(size_t)C + c4*4];
                sA[(c4*4+0)*132 + i] = v.x;
                sA[(c4*4+1)*132 + i] = v.y;
                sA[(c4*4+2)*132 + i] = v.z;
                sA[(c4*4+3)*132 + i] = v.w;
            }
        } else {
            for (int e = t; e < 128*C; e += 256) {
                int i = e / C, c = e - i*C;
                sA[c*132 + i] = H[(baseRow + i0 + i)*(size_t)C + c];
            }
        }
    }

    float td[16]; int ti[16];
    #pragma unroll
    for (int s = 0; s < 16; ++s) { td[s] = INFINITY; ti[s] = 0; }
    const float sqa = SQ[baseRow + i0 + row];

    for (int jt = 0; jt < NN/JT; ++jt) {
        __syncthreads();                 // prev scan done; buffers reusable
        const int j0 = jt*JT;
        if (t < JT) sSqB[t] = SQ[baseRow + j0 + t];

        // fill B chunk 0 into buffer 0
        if (VEC) {
            #pragma unroll
            for (int q = 0; q < (JT*(CHUNK/4))/256; ++q) {
                int j = t & 63;
                int c4 = (t >> 6) + q*4;
                float4 v = *(const float4*)&H[(baseRow + j0 + j)*(size_t)C + c4*4];
                sB[(c4*4+0)*68 + j] = v.x;
                sB[(c4*4+1)*68 + j] = v.y;
                sB[(c4*4+2)*68 + j] = v.z;
                sB[(c4*4+3)*68 + j] = v.w;
            }
        } else {
            for (int e = t; e < JT*CHUNK; e += 256) {
                int j = e / CHUNK, c = e - (e/CHUNK)*CHUNK;
                sB[c*68 + j] = H[(baseRow + j0 + j)*(size_t)C + c];
            }
        }
        // fill A chunk 0 (chunked path)
        if (ACH) {
            #pragma unroll
            for (int q = 0; q < 4; ++q) {
                int i = t & 127;
                int c4 = (t >> 7) + q*2;
                float4 v = *(const float4*)&H[(baseRow + i0 + i)*(size_t)C + c4*4];
                sA[(c4*4+0)*132 + i] = v.x;
                sA[(c4*4+1)*132 + i] = v.y;
                sA[(c4*4+2)*132 + i] = v.z;
                sA[(c4*4+3)*132 + i] = v.w;
            }
        }

        float acc[8][4];
        #pragma unroll
        for (int a=0;a<8;a++)
            #pragma unroll
            for (int c=0;c<4;c++) acc[a][c]=0.f;

        float4 preB[2];
        float4 preA[4];
        for (int ch = 0; ch < NC; ++ch) {
            __syncthreads();
            if (NC > 1 && ch + 1 < NC) {
                const int c0n = (ch+1)*CHUNK;
                #pragma unroll
                for (int q = 0; q < 2; ++q) {
                    int j = t & 63;
                    int c4 = (t >> 6) + q*4;
                    preB[q] = *(const float4*)&H[(baseRow + j0 + j)*(size_t)C + c0n + c4*4];
                }
                if (ACH) {
                    #pragma unroll
                    for (int q = 0; q < 4; ++q) {
                        int i = t & 127;
                        int c4 = (t >> 7) + q*2;
                        preA[q] = *(const float4*)&H[(baseRow + i0 + i)*(size_t)C + c0n + c4*4];
                    }
                }
            }
            const float* aBase = (ACH ? sA + (ch & 1)*(32*132)
                                      : sA + ch*CHUNK*132) + ty*8;
            const float* bBase = sB + (ch & 1)*(CHUNK*68) + tx*4;
            #pragma unroll
            for (int cc = 0; cc < CHUNK; ++cc) {
                float4 a0 = *(const float4*)(aBase + cc*132);
                float4 a1 = *(const float4*)(aBase + cc*132 + 4);
                float4 b0 = *(const float4*)(bBase + cc*68);
                float av[8] = {a0.x,a0.y,a0.z,a0.w,a1.x,a1.y,a1.z,a1.w};
                float bv[4] = {b0.x,b0.y,b0.z,b0.w};
                #pragma unroll
                for (int ri=0;ri<8;ri++)
                    #pragma unroll
                    for (int rj=0;rj<4;rj++)
                        acc[ri][rj] = fmaf(av[ri], bv[rj], acc[ri][rj]);
            }
            if (NC > 1 && ch + 1 < NC) {
                float* dB = sB + ((ch+1) & 1)*(CHUNK*68);
                #pragma unroll
                for (int q = 0; q < 2; ++q) {
                    int j = t & 63;
                    int c4 = (t >> 6) + q*4;
                    dB[(c4*4+0)*68 + j] = preB[q].x;
                    dB[(c4*4+1)*68 + j] = preB[q].y;
                    dB[(c4*4+2)*68 + j] = preB[q].z;
                    dB[(c4*4+3)*68 + j] = preB[q].w;
                }
                if (ACH) {
                    float* dA = sA + ((ch+1) & 1)*(32*132);
                    #pragma unroll
                    for (int q = 0; q < 4; ++q) {
                        int i = t & 127;
                        int c4 = (t >> 7) + q*2;
                        dA[(c4*4+0)*132 + i] = preA[q].x;
                        dA[(c4*4+1)*132 + i] = preA[q].y;
                        dA[(c4*4+2)*132 + i] = preA[q].z;
                        dA[(c4*4+3)*132 + i] = preA[q].w;
                    }
                }
            }
        }
        // write dot tile (exclusive 8x4 region per thread)
        #pragma unroll
        for (int ri=0;ri<8;ri++)
            *(float4*)(sD + (ty*8+ri)*68 + tx*4) =
                make_float4(acc[ri][0],acc[ri][1],acc[ri][2],acc[ri][3]);
        __syncthreads();

        // scan: every thread processes its 32-candidate half of its row
        {
            const float* drow = sD + row*68 + half*32;
            const float* sqb  = sSqB + half*32;
            const int jb = j0 + half*32;
            #pragma unroll
            for (int g = 0; g < 8; ++g) {
                float4 v = *(const float4*)(drow + g*4);
                float dd[4] = {v.x, v.y, v.z, v.w};
                #pragma unroll
                for (int u = 0; u < 4; ++u) {
                    float d = sqa + sqb[g*4+u] - 2.f*dd[u];
                    if (d < td[15]) {
                        int jidx = jb + g*4 + u;
                        #pragma unroll
                        for (int s = 15; s >= 1; --s) {
                            bool cp = td[s-1] > d;
                            bool cs = td[s]   > d;
                            td[s] = cp ? td[s-1] : (cs ? d    : td[s]);
                            ti[s] = cp ? ti[s-1] : (cs ? jidx : ti[s]);
                        }
                        bool c0k = td[0] > d;
                        td[0] = c0k ? d    : td[0];
                        ti[0] = c0k ? jidx : ti[0];
                    }
                }
            }
        }
    }
    __syncthreads();
    // dump both halves' sorted lists into sD (reused as [128][64])
    {
        float* mrow = sD + row*64 + half*32;
        int*   mrowi = (int*)mrow + 16;
        #pragma unroll
        for (int s = 0; s < 16; ++s) { mrow[s] = td[s]; mrowi[s] = ti[s]; }
    }
    __syncthreads();
    // exact merge (lower distance wins; on equal distance, lower index wins)
    if (t < 128) {
        const float* dAl = sD + t*64;
        const int*   iAl = (const int*)dAl + 16;
        const float* dBl = dAl + 32;
        const int*   iBl = iAl + 32;
        int pa = 0, pb = 0;
        int* o = IDX + (baseRow + i0 + t)*KK;
        #pragma unroll
        for (int s = 0; s < 16; ++s) {
            float da = dAl[pa], db = dBl[pb];
            int   ia = iAl[pa], ib = iBl[pb];
            bool takeA = (da < db) || (da == db && ia < ib);
            o[s] = takeA ? ia : ib;
            pa += takeA ? 1 : 0;
            pb += takeA ? 0 : 1;
        }
    }
}

// ---------------- cov features: [x, cov(knn xyz).flatten(9)] -> 12 ch ----------------
__global__ void k_cov(const float* __restrict__ X, const int* __restrict__ IDX,
                      float* __restrict__ OUT){
    int p = blockIdx.x*blockDim.x + threadIdx.x;
    if (p >= NPTS) return;
    int b = p >> 11;
    const int* id = IDX + (size_t)p*KK;
    float px[16], py[16], pz[16];
    float mx=0.f,my=0.f,mz=0.f;
    #pragma unroll
    for (int k=0;k<16;k++){
        int j = id[k];
        const float* q = X + ((size_t)(b<<11) + j)*3;
        px[k]=q[0]; py[k]=q[1]; pz[k]=q[2];
        mx+=px[k]; my+=py[k]; mz+=pz[k];
    }
    mx *= (1.f/16.f); my *= (1.f/16.f); mz *= (1.f/16.f);
    float c00=0,c01=0,c02=0,c11=0,c12=0,c22=0;
    #pragma unroll
    for (int k=0;k<16;k++){
        float cx=px[k]-mx, cy=py[k]-my, cz=pz[k]-mz;
        c00=fmaf(cx,cx,c00); c01=fmaf(cx,cy,c01); c02=fmaf(cx,cz,c02);
        c11=fmaf(cy,cy,c11); c12=fmaf(cy,cz,c12); c22=fmaf(cz,cz,c22);
    }
    const float* xi = X + (size_t)p*3;
    float* o = OUT + (size_t)p*12;
    o[0]=xi[0]; o[1]=xi[1]; o[2]=xi[2];
    o[3]=c00; o[4]=c01; o[5]=c02;
    o[6]=c01; o[7]=c11; o[8]=c12;
    o[9]=c02; o[10]=c12; o[11]=c22;
}

// ---------------- pointwise dense (kernel_size=1 conv), optional BN+ReLU ----------------
template<int CIN,int COUT,int RELU,int BN>
__global__ __launch_bounds__(256) void k_dense(const float* __restrict__ X,
        const float* __restrict__ W, const float* __restrict__ bias,
        const float* __restrict__ bg, const float* __restrict__ bb,
        const float* __restrict__ bm, const float* __restrict__ bv,
        float* __restrict__ OUT){
    extern __shared__ float sm[];
    float* Xs = sm;                  // [64][CIN] (CIN % 4 == 0)
    float* Ws = Xs + 64*CIN;         // [CIN][COUT]
    const int t = threadIdx.x;
    const size_t row0 = (size_t)blockIdx.x * 64;
    for (int e = t; e < (64*CIN)/4; e += 256)
        *(float4*)&Xs[e*4] = *(const float4*)&X[row0*CIN + e*4];
    for (int e = t; e < (CIN*COUT)/4; e += 256)
        *(float4*)&Ws[e*4] = *(const float4*)&W[e*4];
    __syncthreads();
    constexpr int CQ = COUT/4;
    for (int q = t; q < 32*CQ; q += 256) {
        int rp = q / CQ;
        int c4 = (q - rp*CQ)*4;
        float4 b4 = *(const float4*)(bias + c4);
        float a0[4] = {b4.x,b4.y,b4.z,b4.w};
        float a1[4] = {b4.x,b4.y,b4.z,b4.w};
        #pragma unroll 8
        for (int k=0;k<CIN;k++){
            float x0 = Xs[rp*CIN+k];
            float x1 = Xs[(rp+32)*CIN+k];
            float4 w = *(const float4*)(Ws + k*COUT + c4);
            a0[0]=fmaf(x0,w.x,a0[0]); a0[1]=fmaf(x0,w.y,a0[1]);
            a0[2]=fmaf(x0,w.z,a0[2]); a0[3]=fmaf(x0,w.w,a0[3]);
            a1[0]=fmaf(x1,w.x,a1[0]); a1[1]=fmaf(x1,w.y,a1[1]);
            a1[2]=fmaf(x1,w.z,a1[2]); a1[3]=fmaf(x1,w.w,a1[3]);
        }
        #pragma unroll
        for (int u=0;u<4;u++){
            float v0=a0[u], v1=a1[u];
            if (BN){
                int c = c4+u;
                float s   = bg[c]*rsqrtf(bv[c]+1e-3f);
                float off = bb[c] - bm[c]*s;
                v0 = fmaf(v0,s,off); v1 = fmaf(v1,s,off);
            }
            if (RELU){ v0=fmaxf(v0,0.f); v1=fmaxf(v1,0.f); }
            a0[u]=v0; a1[u]=v1;
        }
        *(float4*)(OUT + (row0+rp)*COUT + c4)    = make_float4(a0[0],a0[1],a0[2],a0[3]);
        *(float4*)(OUT + (row0+rp+32)*COUT + c4) = make_float4(a1[0],a1[1],a1[2],a1[3]);
    }
}

// ---------------- gather neighbors + max over k ----------------
template<int C>
__global__ void k_gmax(const float* __restrict__ H, const int* __restrict__ IDX,
                       float* __restrict__ OUT){
    constexpr int CQ = C/4;
    int e = blockIdx.x*blockDim.x + threadIdx.x;
    if (e >= NPTS*CQ) return;
    int p = e / CQ, c4 = (e - p*CQ)*4;
    int b = p >> 11;
    const int* id = IDX + (size_t)p*KK;
    float4 m = make_float4(-INFINITY,-INFINITY,-INFINITY,-INFINITY);
    #pragma unroll
    for (int k=0;k<16;k++){
        int j = id[k];
        float4 v = *(const float4*)(H + ((size_t)(b<<11)+j)*C + c4);
        m.x=fmaxf(m.x,v.x); m.y=fmaxf(m.y,v.y);
        m.z=fmaxf(m.z,v.z); m.w=fmaxf(m.w,v.w);
    }
    *(float4*)(OUT + (size_t)p*C + c4) = m;
}

// ---------------- 128->1024 GEMM fused with bias + global max over N ----------------
// grid (1024/64, N/128, B); 256 threads, 2 CTAs/SM; 8x4 micro-tiles, vector fills.
__global__ __launch_bounds__(256,2) void k_gemm_pool(const float* __restrict__ X,
        const float* __restrict__ W, const float* __restrict__ bias,
        float* __restrict__ pool){
    extern __shared__ float sm[];
    float* XsT  = sm;              // [128 k][132 i]
    float* Ws   = XsT + 128*132;   // [128 k][68 c]
    float* sred = Ws  + 128*68;    // [64 c][17]
    const int t = threadIdx.x, tx = t & 15, ty = t >> 4;
    const int b = blockIdx.z;
    const size_t row0 = (size_t)b*NN + (size_t)blockIdx.y*128;
    const int c0 = blockIdx.x*64;

    #pragma unroll
    for (int q = 0; q < 16; ++q) {
        int i = t & 127;
        int k4 = (t >> 7) + q*2;
        float4 v = *(const float4*)&X[(row0 + i)*128 + k4*4];
        XsT[(k4*4+0)*132 + i] = v.x;
        XsT[(k4*4+1)*132 + i] = v.y;
        XsT[(k4*4+2)*132 + i] = v.z;
        XsT[(k4*4+3)*132 + i] = v.w;
    }
    #pragma unroll
    for (int q = 0; q < 8; ++q) {
        int c4 = t & 15;
        int k = (t >> 4) + q*16;
        *(float4*)&Ws[k*68 + c4*4] = *(const float4*)&W[(size_t)k*1024 + c0 + c4*4];
    }
    __syncthreads();

    float acc[8][4];
    #pragma unroll
    for (int a=0;a<8;a++)
        #pragma unroll
        for (int c=0;c<4;c++) acc[a][c]=0.f;

    const float* aBase = XsT + ty*8;
    const float* wBase = Ws  + tx*4;
    #pragma unroll 8
    for (int k=0;k<128;k++){
        float4 a0 = *(const float4*)(aBase + k*132);
        float4 a1 = *(const float4*)(aBase + k*132 + 4);
        float4 w0 = *(const float4*)(wBase + k*68);
        float av[8] = {a0.x,a0.y,a0.z,a0.w,a1.x,a1.y,a1.z,a1.w};
        float wv[4] = {w0.x,w0.y,w0.z,w0.w};
        #pragma unroll
        for (int ri=0;ri<8;ri++)
            #pragma unroll
            for (int rj=0;rj<4;rj++)
                acc[ri][rj] = fmaf(av[ri], wv[rj], acc[ri][rj]);
    }
    #pragma unroll
    for (int rj=0;rj<4;rj++){
        float m = acc[0][rj];
        #pragma unroll
        for (int ri=1;ri<8;ri++) m = fmaxf(m, acc[ri][rj]);
        sred[(tx*4+rj)*17 + ty] = m;
    }
    __syncthreads();
    if (t < 64){
        float m = sred[t*17];
        #pragma unroll
        for (int q=1;q<16;q++) m = fmaxf(m, sred[t*17+q]);
        m += bias[c0 + t];
        atomicMaxF(&pool[b*1024 + c0 + t], m);
    }
}

__global__ void k_init(float* __restrict__ p, int n){
    int e = blockIdx.x*blockDim.x + threadIdx.x;
    if (e < n) p[e] = -INFINITY;
}

// ---------------- tiny FC layers over pooled [B, CIN] ----------------
template<int CIN,int COUT,int RELU>
__global__ __launch_bounds__(256) void k_fc(const float* __restrict__ IN,
        const float* __restrict__ W, const float* __restrict__ bias,
        float* __restrict__ OUT){
    __shared__ float Ps[CIN];
    const int t = threadIdx.x;
    const int b = blockIdx.y;
    const int c = blockIdx.x*256 + t;
    for (int e=t;e<CIN;e+=256) Ps[e]=IN[b*CIN+e];
    __syncthreads();
    float acc = bias[c];
    #pragma unroll 8
    for (int k=0;k<CIN;k++) acc = fmaf(Ps[k], W[(size_t)k*COUT + c], acc);
    if (RELU) acc = fmaxf(acc, 0.f);
    OUT[b*COUT + c] = acc;
}

// ---------------- host ----------------
static inline int knn_smem(int C){
    int ch = C < 32 ? C : 32;
    int sa = (C > 64) ? 2*32*132 : C*132;
    return (sa + 2*ch*68 + 128*68 + 64)*4;
}
static inline int dense_smem(int cin, int cout){
    return (64*cin + cin*cout)*4;
}
#define GEMM_SMEM ((128*132 + 128*68 + 64*17)*4)

extern "C" void kernel_launch(void* const* d_in, const int* in_sizes, int n_in,
                              void* d_out, int out_size){
    const float* x    = (const float*)d_in[0];
    const float* c1w  = (const float*)d_in[1];
    const float* c1b  = (const float*)d_in[2];
    const float* c2w  = (const float*)d_in[3];
    const float* c2b  = (const float*)d_in[4];
    const float* c3w  = (const float*)d_in[5];
    const float* c3b  = (const float*)d_in[6];
    const float* g1lw = (const float*)d_in[7];
    const float* g1lb = (const float*)d_in[8];
    const float* g1cw = (const float*)d_in[9];
    const float* g1cb = (const float*)d_in[10];
    const float* g2lw = (const float*)d_in[11];
    const float* g2lb = (const float*)d_in[12];
    const float* g2cw = (const float*)d_in[13];
    const float* g2cb = (const float*)d_in[14];
    const float* c4w  = (const float*)d_in[15];
    const float* c4b  = (const float*)d_in[16];
    const float* c5w  = (const float*)d_in[17];
    const float* c5b  = (const float*)d_in[18];
    const float* bn1g = (const float*)d_in[19];
    const float* bn1b = (const float*)d_in[20];
    const float* bn1m = (const float*)d_in[21];
    const float* bn1v = (const float*)d_in[22];
    const float* bn2g = (const float*)d_in[23];
    const float* bn2b = (const float*)d_in[24];
    const float* bn2m = (const float*)d_in[25];
    const float* bn2v = (const float*)d_in[26];
    const float* bn3g = (const float*)d_in[27];
    const float* bn3b = (const float*)d_in[28];
    const float* bn3m = (const float*)d_in[29];
    const float* bn3v = (const float*)d_in[30];
    float* out = (float*)d_out;

    float *A,*B,*SQ,*POOL,*Y; int* ID;
    cudaGetSymbolAddress((void**)&A, gA);
    cudaGetSymbolAddress((void**)&B, gB);
    cudaGetSymbolAddress((void**)&SQ, gSq);
    cudaGetSymbolAddress((void**)&POOL, gPool);
    cudaGetSymbolAddress((void**)&Y, gY);
    cudaGetSymbolAddress((void**)&ID, gIdx);

    cudaFuncSetAttribute(k_knn<3>,   cudaFuncAttributeMaxDynamicSharedMemorySize, knn_smem(3));
    cudaFuncSetAttribute(k_knn<64>,  cudaFuncAttributeMaxDynamicSharedMemorySize, knn_smem(64));
    cudaFuncSetAttribute(k_knn<128>, cudaFuncAttributeMaxDynamicSharedMemorySize, knn_smem(128));
    cudaFuncSetAttribute(k_gemm_pool, cudaFuncAttributeMaxDynamicSharedMemorySize, GEMM_SMEM);
    cudaFuncSetAttribute((void*)k_dense<64,128,1,0>, cudaFuncAttributeMaxDynamicSharedMemorySize,
                         dense_smem(64,128));
    cudaFuncSetAttribute((void*)k_dense<128,128,0,0>, cudaFuncAttributeMaxDynamicSharedMemorySize,
                         dense_smem(128,128));

    const dim3 knnGrid(NN/128, BB);

    // stage 0: knn on xyz + covariance features
    k_sq<<<(NPTS*32)/256, 256>>>(x, SQ, 3);
    k_knn<3><<<knnGrid, 256, knn_smem(3)>>>(x, SQ, ID);
    k_cov<<<NPTS/256, 256>>>(x, ID, A);                       // A: [*,12]

    // MLP stack with BN+ReLU
    k_dense<12,12,1,1><<<NPTS/64, 256, dense_smem(12,12)>>>(A, c1w, c1b, bn1g,bn1b,bn1m,bn1v, B);
    k_dense<12,64,1,1><<<NPTS/64, 256, dense_smem(12,64)>>>(B, c2w, c2b, bn2g,bn2b,bn2m,bn2v, A);
    k_dense<64,64,1,1><<<NPTS/64, 256, dense_smem(64,64)>>>(A, c3w, c3b, bn3g,bn3b,bn3m,bn3v, B); // h64 in B

    // graph layer 1 (C=64 -> 128, relu)
    k_sq<<<(NPTS*32)/256, 256>>>(B, SQ, 64);
    k_knn<64><<<knnGrid, 256, knn_smem(64)>>>(B, SQ, ID);
    k_gmax<64><<<(NPTS*16)/256, 256>>>(B, ID, A);
    k_dense<64,64,0,0><<<NPTS/64, 256, dense_smem(64,64)>>>(A, g1lw, g1lb, 0,0,0,0, B);
    k_dense<64,128,1,0><<<NPTS/64, 256, dense_smem(64,128)>>>(B, g1cw, g1cb, 0,0,0,0, A); // h128 in A

    // graph layer 2 (C=128 -> 1024, no relu) fused with global max pool
    k_sq<<<(NPTS*32)/256, 256>>>(A, SQ, 128);
    k_knn<128><<<knnGrid, 256, knn_smem(128)>>>(A, SQ, ID);
    k_gmax<128><<<(NPTS*32)/256, 256>>>(A, ID, B);
    k_dense<128,128,0,0><<<NPTS/64, 256, dense_smem(128,128)>>>(B, g2lw, g2lb, 0,0,0,0, A);
    k_init<<<(BB*1024)/256, 256>>>(POOL, BB*1024);
    k_gemm_pool<<<dim3(1024/64, NN/128, BB), 256, GEMM_SMEM>>>(A, g2cw, g2cb, POOL);

    // head
    k_fc<1024,1024,1><<<dim3(1024/256, BB), 256>>>(POOL, c4w, c4b, Y);
    k_fc<1024,512,0><<<dim3(512/256, BB), 256>>>(Y, c5w, c5b, out);
}